// round 17
// baseline (speedup 1.0000x reference)
#include <cuda_runtime.h>
#include <cuda_fp16.h>
#include <math.h>
#include <stdint.h>

#define S_LEN 2048
#define EDIM 1024
#define NHEAD 16
#define HD 64
#define BATCH 2
#define MROWS (BATCH * S_LEN)        // 4096
// softmax in exp2 domain: fold 1/head_dim * log2(e) into Q projection
#define QSCALE (1.4426950408889634f / 64.0f)

// Scratch (device globals; no allocations allowed) — all fp16
__device__ __half g_q[BATCH * NHEAD * S_LEN * HD];
__device__ __half g_k[BATCH * NHEAD * S_LEN * HD];
__device__ __half g_v[BATCH * NHEAD * S_LEN * HD];
__device__ __half g_attn[MROWS * EDIM];
__device__ __half g_xh[MROWS * EDIM];
__device__ __half g_wh[4 * EDIM * EDIM];

// GEMM: tile 128x256, BK=64, 3 stages.
// A stage: 128 rows x 72 halfs = 18432B. B stage: 64 rows x 264 halfs = 33792B.
#define GA_H 72
#define GB_H 264
#define GA_B 18432
#define G_STG 52224                       // 18432 + 33792
#define GEMM_SMEM (3 * G_STG)             // 156672
// Flash smem: 3 stages of (K 64x72 halfs + V 64x72 halfs); F_KV is BYTES per tile
#define F_H 72
#define F_KV 9216
#define F_STG (2 * F_KV)                  // 18432
#define FLASH_SMEM (3 * F_STG)            // 55296

// ---------------------------------------------------------------------------
// helpers
// ---------------------------------------------------------------------------
__device__ __forceinline__ float ex2f(float x) {
    float y;
    asm("ex2.approx.ftz.f32 %0, %1;" : "=f"(y) : "f"(x));
    return y;
}
__device__ __forceinline__ void ldm4(uint32_t* r, uint32_t addr) {
    asm volatile("ldmatrix.sync.aligned.m8n8.x4.shared.b16 {%0,%1,%2,%3}, [%4];"
                 : "=r"(r[0]), "=r"(r[1]), "=r"(r[2]), "=r"(r[3]) : "r"(addr));
}
__device__ __forceinline__ void ldm4t(uint32_t* r, uint32_t addr) {
    asm volatile("ldmatrix.sync.aligned.m8n8.x4.trans.shared.b16 {%0,%1,%2,%3}, [%4];"
                 : "=r"(r[0]), "=r"(r[1]), "=r"(r[2]), "=r"(r[3]) : "r"(addr));
}
__device__ __forceinline__ void cp16(uint32_t smem_dst, const void* gsrc) {
    asm volatile("cp.async.cg.shared.global [%0], [%1], 16;"
                 :: "r"(smem_dst), "l"(gsrc));
}
__device__ __forceinline__ void cp_commit() {
    asm volatile("cp.async.commit_group;");
}
// c += A(16x16 f16) * B(16x8 f16), fp32 accum
__device__ __forceinline__ void mma16(float* c, uint32_t a0, uint32_t a1,
                                      uint32_t a2, uint32_t a3,
                                      uint32_t b0, uint32_t b1) {
    asm volatile(
        "mma.sync.aligned.m16n8k16.row.col.f32.f16.f16.f32 "
        "{%0,%1,%2,%3}, {%4,%5,%6,%7}, {%8,%9}, {%0,%1,%2,%3};\n"
        : "+f"(c[0]), "+f"(c[1]), "+f"(c[2]), "+f"(c[3])
        : "r"(a0), "r"(a1), "r"(a2), "r"(a3), "r"(b0), "r"(b1));
}
__device__ __forceinline__ uint32_t h2u(float a, float b) {
    __half2 h = __floats2half2_rn(a, b);
    return *reinterpret_cast<uint32_t*>(&h);
}

// ---------------------------------------------------------------------------
// fused fp32 -> fp16 convert: x (4096 blks), then wq/wk/wv/wo (1024 blks each)
// ---------------------------------------------------------------------------
__global__ __launch_bounds__(256) void conv_all(const float* __restrict__ x,
                                                const float* __restrict__ wq,
                                                const float* __restrict__ wk,
                                                const float* __restrict__ wv,
                                                const float* __restrict__ wo,
                                                __half* __restrict__ xh,
                                                __half* __restrict__ wh)
{
    const int bx = blockIdx.x;
    const float* src;
    __half* dst;
    size_t off;
    if (bx < 4096) {
        src = x; dst = xh; off = (size_t)bx * 1024;
    } else {
        const int z = (bx - 4096) >> 10;
        src = (z == 0) ? wq : (z == 1) ? wk : (z == 2) ? wv : wo;
        dst = wh + (size_t)z * EDIM * EDIM;
        off = (size_t)((bx - 4096) & 1023) * 1024;
    }
    const size_t i = off + threadIdx.x * 4;
    float4 v = *(const float4*)(src + i);
    *(__half2*)(dst + i)     = __floats2half2_rn(v.x, v.y);
    *(__half2*)(dst + i + 2) = __floats2half2_rn(v.z, v.w);
}

// ---------------------------------------------------------------------------
// fp16 GEMM core: C tile = A[m0..,:] @ W[:, n0..] + bias
// Tile 128x256, BK=64, 256 threads (8 warps 2x4, warp tile 64x64),
// 3-stage cp.async ring, 1 sync per 64-k chunk (16 total).
// ---------------------------------------------------------------------------
__device__ __forceinline__ void gemm_body(const __half* __restrict__ A,
                                          const __half* __restrict__ W,
                                          const float* __restrict__ bias,
                                          void* __restrict__ Cout,
                                          int m0, int n0, int mode, float scale)
{
    extern __shared__ __half sm[];
    const uint32_t sbase = (uint32_t)__cvta_generic_to_shared(sm);
    const int tid = threadIdx.x;
    const int lane = tid & 31;
    const int wid = tid >> 5;
    const int wm = wid & 1;             // 2 warps along M (64 rows each)
    const int wn = wid >> 1;            // 4 warps along N (64 cols each)

    // cp.async assignments:
    // A 128x64 halfs: 2 thr/row, 32-half segments, 4 chunks each.
    // B 64x256 halfs: 4 thr/row, 64-half segments, 8 chunks each.
    const int arow = tid >> 1;
    const int aseg = (tid & 1) << 5;
    const int brow = tid >> 2;
    const int bseg = (tid & 3) << 6;

    const __half* ag = A + (size_t)(m0 + arow) * EDIM + aseg;
    const __half* wg = W + (size_t)brow * EDIM + n0 + bseg;

    auto issue = [&](int kc) {
        const int st = kc % 3;
        const uint32_t ab = sbase + st * G_STG;
        const uint32_t bb = ab + GA_B;
        const __half* a = ag + (kc << 6);
        const __half* w = wg + (size_t)(kc << 6) * EDIM;
#pragma unroll
        for (int u = 0; u < 4; u++)
            cp16(ab + (arow * GA_H + aseg + (u << 3)) * 2, a + (u << 3));
#pragma unroll
        for (int u = 0; u < 8; u++)
            cp16(bb + (brow * GB_H + bseg + (u << 3)) * 2, w + (u << 3));
        cp_commit();
    };

    float acc[4][8][4];
#pragma unroll
    for (int i = 0; i < 4; i++)
#pragma unroll
        for (int j = 0; j < 8; j++)
#pragma unroll
            for (int c = 0; c < 4; c++) acc[i][j][c] = 0.0f;

    issue(0);
    issue(1);

    const int lrow16 = lane & 15;
    const int lhi = (lane >> 4) << 3;

    for (int kc = 0; kc < 16; kc++) {
        if (kc < 15) asm volatile("cp.async.wait_group 1;");
        else         asm volatile("cp.async.wait_group 0;");
        __syncthreads();
        if (kc + 2 < 16) issue(kc + 2);

        const int st = kc % 3;
        const uint32_t ab = sbase + st * G_STG;
        const uint32_t bb = ab + GA_B;

#pragma unroll
        for (int ks = 0; ks < 4; ks++) {
            uint32_t a[4][4];
#pragma unroll
            for (int i = 0; i < 4; i++)
                ldm4(a[i], ab + (((wm << 6) + (i << 4) + lrow16) * GA_H
                                 + (ks << 4) + lhi) * 2);
            uint32_t b[4][4];
#pragma unroll
            for (int jt = 0; jt < 4; jt++)
                ldm4t(b[jt], bb + (((ks << 4) + lrow16) * GB_H
                                   + (wn << 6) + (jt << 4) + lhi) * 2);
#pragma unroll
            for (int i = 0; i < 4; i++)
#pragma unroll
                for (int j = 0; j < 8; j++)
                    mma16(acc[i][j], a[i][0], a[i][1], a[i][2], a[i][3],
                          b[j >> 1][(j & 1) << 1], b[j >> 1][((j & 1) << 1) + 1]);
        }
    }

    const int tq = lane >> 2;
    const int tr = lane & 3;
#pragma unroll
    for (int i = 0; i < 4; i++) {
#pragma unroll
        for (int j = 0; j < 8; j++) {
            const int row = m0 + (wm << 6) + (i << 4) + tq;
            const int col = n0 + (wn << 6) + (j << 3) + (tr << 1);
            const float b0 = bias[col], b1 = bias[col + 1];
            if (mode == 0) {
                float* C = (float*)Cout;
                *(float2*)&C[(size_t)row * EDIM + col] =
                    make_float2(acc[i][j][0] + b0, acc[i][j][1] + b1);
                *(float2*)&C[(size_t)(row + 8) * EDIM + col] =
                    make_float2(acc[i][j][2] + b0, acc[i][j][3] + b1);
            } else {
                __half* C = (__half*)Cout;
                const int h = col >> 6, d = col & 63;
#pragma unroll
                for (int rr = 0; rr < 2; rr++) {
                    const int r = row + (rr << 3);
                    const int bb2 = r >> 11;
                    const int s = r & (S_LEN - 1);
                    size_t dst = ((size_t)((bb2 * NHEAD + h) * S_LEN + s)) * HD + d;
                    *(__half2*)&C[dst] = __floats2half2_rn(
                        (acc[i][j][(rr << 1) + 0] + b0) * scale,
                        (acc[i][j][(rr << 1) + 1] + b1) * scale);
                }
            }
        }
    }
}

// fused Q/K/V projection: grid.x = 12 (4 n-blocks x 3 weights)
__global__ __launch_bounds__(256) void gemm_qkv(const __half* __restrict__ A,
                                                const __half* __restrict__ wh,
                                                const float* __restrict__ bq,
                                                const float* __restrict__ bk,
                                                const float* __restrict__ bv,
                                                __half* __restrict__ qp,
                                                __half* __restrict__ kp,
                                                __half* __restrict__ vp)
{
    const int z = blockIdx.x >> 2;
    const int n0 = (blockIdx.x & 3) << 8;
    const int m0 = blockIdx.y << 7;
    const __half* W = wh + (size_t)z * EDIM * EDIM;
    const float* bias = (z == 0) ? bq : (z == 1) ? bk : bv;
    __half* out = (z == 0) ? qp : (z == 1) ? kp : vp;
    gemm_body(A, W, bias, out, m0, n0, 1, (z == 0) ? (float)QSCALE : 1.0f);
}

// output projection
__global__ __launch_bounds__(256) void gemm_out(const __half* __restrict__ A,
                                                const __half* __restrict__ W,
                                                const float* __restrict__ bias,
                                                float* __restrict__ out)
{
    gemm_body(A, W, bias, out, blockIdx.y << 7, blockIdx.x << 8, 0, 1.0f);
}

// ---------------------------------------------------------------------------
// fp16 flash attention (mask keeps j >= i). Bq=128, Bk=64, 256 threads
// (8 warps x 16 q rows). K+V in one 3-stage cp.async ring, ONE sync per tile.
// Warp-group wg = wid>>2 owns q 64-block (2qb+wg); it skips t < wg (fully
// masked) and applies the triangular mask at t == wg.
// ---------------------------------------------------------------------------
__global__ __launch_bounds__(256) void flash_h(const __half* __restrict__ Q,
                                               const __half* __restrict__ K,
                                               const __half* __restrict__ V,
                                               __half* __restrict__ O)
{
    extern __shared__ __half smf[];
    const uint32_t sbase = (uint32_t)__cvta_generic_to_shared(smf);

    const int tid = threadIdx.x;
    const int lane = tid & 31;
    const int wid = tid >> 5;          // 0..7
    const int wg = wid >> 2;           // 0/1: q rows 0-63 / 64-127
    const int qb = blockIdx.x;         // 0..15 (q block of 128 rows)
    const int bh = blockIdx.y;
    const int q0 = qb << 7;
    const size_t base = (size_t)bh * S_LEN * HD;

    const int tq = lane >> 2;
    const int tr = lane & 3;
    const int lrow16 = lane & 15;
    const int lhi = (lane >> 4) << 3;

    const int T = (S_LEN / 64) - (qb << 1);

    auto issue = [&](int t) {
        const int st = t % 3;
        const uint32_t kb = sbase + st * F_STG;
        const size_t gbase = base + (((size_t)(qb << 1) + t) << 6) * HD;
#pragma unroll
        for (int i = 0; i < 2; i++) {
            const int c = tid + (i << 8);       // 0..511
            const int row = c >> 3;
            const int seg = (c & 7) << 3;       // halfs
            const uint32_t doff = (row * F_H + seg) * 2;
            cp16(kb + doff, K + gbase + (size_t)row * HD + seg);
            cp16(kb + F_KV + doff, V + gbase + (size_t)row * HD + seg);
        }
        cp_commit();
    };

    // Q fragments from global fp16, PTX order
    uint32_t qa[4][4];
    {
        const __half* Qr = Q + base + (size_t)(q0 + (wid << 4) + tq) * HD;
#pragma unroll
        for (int ks = 0; ks < 4; ks++) {
            qa[ks][0] = *(const uint32_t*)(Qr + (ks << 4) + (tr << 1));
            qa[ks][1] = *(const uint32_t*)(Qr + (HD << 3) + (ks << 4) + (tr << 1));
            qa[ks][2] = *(const uint32_t*)(Qr + (ks << 4) + 8 + (tr << 1));
            qa[ks][3] = *(const uint32_t*)(Qr + (HD << 3) + (ks << 4) + 8 + (tr << 1));
        }
    }

    float o[8][4];
#pragma unroll
    for (int j = 0; j < 8; j++)
#pragma unroll
        for (int c = 0; c < 4; c++) o[j][c] = 0.0f;
    float m0 = -INFINITY, m1 = -INFINITY, l0 = 0.0f, l1 = 0.0f;

    issue(0);
    if (T > 1) issue(1);

    for (int t = 0; t < T; t++) {
        if (t + 1 < T) asm volatile("cp.async.wait_group 1;");
        else           asm volatile("cp.async.wait_group 0;");
        __syncthreads();
        if (t + 2 < T) issue(t + 2);

        if (t < wg) continue;   // fully masked tile for this warp-group

        const int st = t % 3;
        const uint32_t sK = sbase + st * F_STG;
        const uint32_t sV = sK + F_KV;

        // S = Q @ K^T
        float s[8][4];
#pragma unroll
        for (int j = 0; j < 8; j++)
#pragma unroll
            for (int c = 0; c < 4; c++) s[j][c] = 0.0f;

#pragma unroll
        for (int ks = 0; ks < 4; ks++) {
            uint32_t b[4][4];
#pragma unroll
            for (int kt = 0; kt < 4; kt++)
                ldm4(b[kt], sK + (((kt << 4) + lrow16) * F_H + (ks << 4) + lhi) * 2);
#pragma unroll
            for (int kt = 0; kt < 4; kt++) {
                mma16(s[(kt << 1) + 0], qa[ks][0], qa[ks][1], qa[ks][2], qa[ks][3],
                      b[kt][0], b[kt][2]);
                mma16(s[(kt << 1) + 1], qa[ks][0], qa[ks][1], qa[ks][2], qa[ks][3],
                      b[kt][1], b[kt][3]);
            }
        }

        // diagonal block: keep key >= q (local row within this 64-block)
        if (t == wg) {
            const int r0l = ((wid & 3) << 4) + tq;
#pragma unroll
            for (int j = 0; j < 8; j++) {
                const int c0 = (j << 3) + (tr << 1);
                if (c0 < r0l)     s[j][0] = -INFINITY;
                if (c0 + 1 < r0l) s[j][1] = -INFINITY;
                if (c0 < r0l + 8)     s[j][2] = -INFINITY;
                if (c0 + 1 < r0l + 8) s[j][3] = -INFINITY;
            }
        }

        // online softmax
        float rmax0 = -INFINITY, rmax1 = -INFINITY;
#pragma unroll
        for (int j = 0; j < 8; j++) {
            rmax0 = fmaxf(rmax0, fmaxf(s[j][0], s[j][1]));
            rmax1 = fmaxf(rmax1, fmaxf(s[j][2], s[j][3]));
        }
#pragma unroll
        for (int off = 1; off <= 2; off <<= 1) {
            rmax0 = fmaxf(rmax0, __shfl_xor_sync(0xffffffffu, rmax0, off));
            rmax1 = fmaxf(rmax1, __shfl_xor_sync(0xffffffffu, rmax1, off));
        }
        const float mn0 = fmaxf(m0, rmax0);
        const float mn1 = fmaxf(m1, rmax1);
        const float fac0 = ex2f(m0 - mn0);
        const float fac1 = ex2f(m1 - mn1);
        float sum0 = 0.0f, sum1 = 0.0f;
#pragma unroll
        for (int j = 0; j < 8; j++) {
            s[j][0] = ex2f(s[j][0] - mn0);
            s[j][1] = ex2f(s[j][1] - mn0);
            s[j][2] = ex2f(s[j][2] - mn1);
            s[j][3] = ex2f(s[j][3] - mn1);
            sum0 += s[j][0] + s[j][1];
            sum1 += s[j][2] + s[j][3];
        }
#pragma unroll
        for (int off = 1; off <= 2; off <<= 1) {
            sum0 += __shfl_xor_sync(0xffffffffu, sum0, off);
            sum1 += __shfl_xor_sync(0xffffffffu, sum1, off);
        }
        l0 = l0 * fac0 + sum0;  m0 = mn0;
        l1 = l1 * fac1 + sum1;  m1 = mn1;
#pragma unroll
        for (int j = 0; j < 8; j++) {
            o[j][0] *= fac0; o[j][1] *= fac0;
            o[j][2] *= fac1; o[j][3] *= fac1;
        }

        // O += P @ V : P packed to half2 (native A-frag layout), V via trans
#pragma unroll
        for (int g = 0; g < 4; g++) {
            const uint32_t p0 = h2u(s[(g << 1)][0],     s[(g << 1)][1]);
            const uint32_t p1 = h2u(s[(g << 1)][2],     s[(g << 1)][3]);
            const uint32_t p2 = h2u(s[(g << 1) + 1][0], s[(g << 1) + 1][1]);
            const uint32_t p3 = h2u(s[(g << 1) + 1][2], s[(g << 1) + 1][3]);
#pragma unroll
            for (int dt = 0; dt < 4; dt++) {
                uint32_t b[4];
                ldm4t(b, sV + (((g << 4) + lrow16) * F_H + (dt << 4) + lhi) * 2);
                mma16(o[(dt << 1) + 0], p0, p1, p2, p3, b[0], b[1]);
                mma16(o[(dt << 1) + 1], p0, p1, p2, p3, b[2], b[3]);
            }
        }
    }

    // epilogue: normalize, write fp16 [B,S,D]
    const float inv0 = 1.0f / l0;
    const float inv1 = 1.0f / l1;
    const int b = bh >> 4;
    const int h = bh & 15;
    const int r0g = q0 + (wid << 4) + tq;
#pragma unroll
    for (int j = 0; j < 8; j++) {
        const int col = (h << 6) + (j << 3) + (tr << 1);
        *(__half2*)&O[((size_t)(b * S_LEN + r0g)) * EDIM + col] =
            __floats2half2_rn(o[j][0] * inv0, o[j][1] * inv0);
        *(__half2*)&O[((size_t)(b * S_LEN + r0g + 8)) * EDIM + col] =
            __floats2half2_rn(o[j][2] * inv1, o[j][3] * inv1);
    }
}

// ---------------------------------------------------------------------------
extern "C" void kernel_launch(void* const* d_in, const int* in_sizes, int n_in,
                              void* d_out, int out_size)
{
    (void)in_sizes; (void)n_in; (void)out_size;
    const float* x  = (const float*)d_in[0];
    const float* wq = (const float*)d_in[1];
    const float* bq = (const float*)d_in[2];
    const float* wk = (const float*)d_in[3];
    const float* bk = (const float*)d_in[4];
    const float* wv = (const float*)d_in[5];
    const float* bv = (const float*)d_in[6];
    const float* wo = (const float*)d_in[7];
    const float* bo = (const float*)d_in[8];
    float* out = (float*)d_out;

    cudaFuncSetAttribute(gemm_qkv, cudaFuncAttributeMaxDynamicSharedMemorySize,
                         GEMM_SMEM);
    cudaFuncSetAttribute(gemm_out, cudaFuncAttributeMaxDynamicSharedMemorySize,
                         GEMM_SMEM);
    cudaFuncSetAttribute(flash_h, cudaFuncAttributeMaxDynamicSharedMemorySize,
                         FLASH_SMEM);

    __half *qp, *kp, *vp, *ap, *xh, *wh;
    cudaGetSymbolAddress((void**)&qp, g_q);
    cudaGetSymbolAddress((void**)&kp, g_k);
    cudaGetSymbolAddress((void**)&vp, g_v);
    cudaGetSymbolAddress((void**)&ap, g_attn);
    cudaGetSymbolAddress((void**)&xh, g_xh);
    cudaGetSymbolAddress((void**)&wh, g_wh);

    conv_all<<<4096 + 4 * 1024, 256>>>(x, wq, wk, wv, wo, xh, wh);

    gemm_qkv<<<dim3(12, MROWS / 128), 256, GEMM_SMEM>>>(xh, wh, bq, bk, bv,
                                                        qp, kp, vp);

    flash_h<<<dim3(S_LEN / 128, BATCH * NHEAD), 256, FLASH_SMEM>>>(qp, kp, vp, ap);

    gemm_out<<<dim3(4, MROWS / 128), 256, GEMM_SMEM>>>(
        ap, wh + 3 * (size_t)EDIM * EDIM, bo, out);
}